// round 5
// baseline (speedup 1.0000x reference)
#include <cuda_runtime.h>
#include <math.h>

#define B_    512
#define T_    8
#define H_    512
#define K1PAD 544   // 513 padded to multiple of 32

#define BM 64
#define BN 64
#define BK 32
#define SSTRIDE 36  // 32 + 4 pad, conflict-free

// ---------------- scratch (static device globals; no allocation) ----------------
__device__ float g_gi[B_ * T_ * 3 * H_];   // 4096 x 1536 precomputed input gates
__device__ float g_gh[B_ * 3 * H_];        // 512 x 1536 hidden gates
__device__ float g_h [B_ * H_];            // hidden state
__device__ float g_z1[B_ * 2 * H_];        // 512 x 1024
__device__ float g_z2[B_ * 2 * H_];        // 512 x 1024
__device__ float g_kb[B_ * H_];            // current RK k
__device__ float g_ks[B_ * H_];            // RK weighted sum
__device__ float g_W1p[2 * H_ * K1PAD];    // W1 padded to K=544

// ---------------- helpers ----------------
__device__ __forceinline__ unsigned f2tf(float f) {
    unsigned u;
    asm("cvt.rna.tf32.f32 %0, %1;" : "=r"(u) : "f"(f));
    return u;
}

__device__ __forceinline__ void mma8(float* c, const unsigned* a, const unsigned* b) {
    asm volatile(
        "mma.sync.aligned.m16n8k8.row.col.f32.tf32.tf32.f32 "
        "{%0,%1,%2,%3}, {%4,%5,%6,%7}, {%8,%9}, {%0,%1,%2,%3};"
        : "+f"(c[0]), "+f"(c[1]), "+f"(c[2]), "+f"(c[3])
        : "r"(a[0]), "r"(a[1]), "r"(a[2]), "r"(a[3]), "r"(b[0]), "r"(b[1]));
}

// ---------------- GEMM workhorse ----------------
// C[M,N] = epi(A[M,K] @ Wt[N,K]^T + bias), tf32 MMA, fp32 accumulate.
// AMODE 0: A plain row-major fp32 (K % 32 == 0, rows 16B-aligned).
// AMODE 1: A built on the fly: col k<512: h[r,k] + cc*dt[r]*kprev[r,k];
//          k==512: t0[r] + salpha*dt[r]; k>512: 0.  (K == K1PAD)
// EPI 0: C = v
// EPI 1: C = swish(v)
// EPI 2: kbuf = v; ksum = v            (RK k1)
// EPI 3: kbuf = v; ksum += 2*v         (RK k2/k3)
// EPI 4: h += dt/6 * (ksum + v)        (RK k4 + state update)
template<int AMODE, int EPI>
__global__ void __launch_bounds__(256)
gemm_tc(const float* __restrict__ A, const float* __restrict__ Wt,
        const float* __restrict__ bias, float* __restrict__ C,
        int N, int K,
        const float* __restrict__ ts_, int tt, float salpha, float cc,
        const float* __restrict__ kprev,
        float* __restrict__ kbuf, float* __restrict__ ksum,
        float* __restrict__ hupd)
{
    __shared__ unsigned sA[BM * SSTRIDE];
    __shared__ unsigned sB[BN * SSTRIDE];

    const int tid  = threadIdx.x;
    const int lane = tid & 31;
    const int warp = tid >> 5;
    const int wm   = warp >> 2;   // 0..1  (32 rows each)
    const int wn   = warp & 3;    // 0..3  (16 cols each)
    const int g    = lane >> 2;
    const int tg   = lane & 3;

    const int row0    = blockIdx.y * BM;
    const int colbase = blockIdx.x * BN;

    float acc[2][2][4];
#pragma unroll
    for (int a = 0; a < 2; a++)
#pragma unroll
        for (int b = 0; b < 2; b++)
#pragma unroll
            for (int e = 0; e < 4; e++) acc[a][b][e] = 0.f;

    float4 ar[2];
    float4 br[2];

    auto load_chunk = [&](int k0) {
#pragma unroll
        for (int i = 0; i < 2; i++) {           // A: 64x32 = 512 float4
            int idx = tid + i * 256;
            int row = idx >> 3;
            int col = (idx & 7) * 4;
            int grow = row0 + row;
            if (AMODE == 0) {
                ar[i] = *(const float4*)(A + (size_t)grow * K + k0 + col);
            } else {
                float t1v = ts_[grow * T_ + tt];
                float t0  = (tt == 0) ? ts_[grow * T_] : ts_[grow * T_ + tt - 1];
                float dt  = (t1v - t0) * 0.25f;
                float cdt = cc * dt;
                float vals[4];
#pragma unroll
                for (int e = 0; e < 4; e++) {
                    int k = k0 + col + e;
                    float v;
                    if (k < H_) {
                        v = A[grow * H_ + k];
                        if (cc != 0.f) v += cdt * kprev[grow * H_ + k];
                    } else if (k == H_) {
                        v = t0 + salpha * dt;
                    } else {
                        v = 0.f;
                    }
                    vals[e] = v;
                }
                ar[i] = make_float4(vals[0], vals[1], vals[2], vals[3]);
            }
        }
#pragma unroll
        for (int i = 0; i < 2; i++) {           // B: 64x32
            int idx = tid + i * 256;
            int row = idx >> 3;
            int col = (idx & 7) * 4;
            br[i] = *(const float4*)(Wt + (size_t)(colbase + row) * K + k0 + col);
        }
    };

    auto stage = [&]() {
#pragma unroll
        for (int i = 0; i < 2; i++) {
            int idx = tid + i * 256;
            int row = idx >> 3;
            int col = (idx & 7) * 4;
            uint4 u;
            u.x = f2tf(ar[i].x); u.y = f2tf(ar[i].y);
            u.z = f2tf(ar[i].z); u.w = f2tf(ar[i].w);
            *(uint4*)(sA + row * SSTRIDE + col) = u;
        }
#pragma unroll
        for (int i = 0; i < 2; i++) {
            int idx = tid + i * 256;
            int row = idx >> 3;
            int col = (idx & 7) * 4;
            uint4 u;
            u.x = f2tf(br[i].x); u.y = f2tf(br[i].y);
            u.z = f2tf(br[i].z); u.w = f2tf(br[i].w);
            *(uint4*)(sB + row * SSTRIDE + col) = u;
        }
    };

    const int nch = K / BK;
    load_chunk(0);
    stage();
    __syncthreads();

    for (int ch = 0; ch < nch; ch++) {
        bool more = (ch + 1 < nch);
        if (more) load_chunk((ch + 1) * BK);

#pragma unroll
        for (int ks = 0; ks < 4; ks++) {
            unsigned af[2][4];
#pragma unroll
            for (int mt = 0; mt < 2; mt++) {
                int r = wm * 32 + mt * 16 + g;
                int base = r * SSTRIDE + ks * 8 + tg;
                af[mt][0] = sA[base];
                af[mt][1] = sA[base + 8 * SSTRIDE];
                af[mt][2] = sA[base + 4];
                af[mt][3] = sA[base + 8 * SSTRIDE + 4];
            }
#pragma unroll
            for (int nt = 0; nt < 2; nt++) {
                int n = wn * 16 + nt * 8 + g;
                unsigned bf[2];
                bf[0] = sB[n * SSTRIDE + ks * 8 + tg];
                bf[1] = sB[n * SSTRIDE + ks * 8 + tg + 4];
                mma8(acc[0][nt], af[0], bf);
                mma8(acc[1][nt], af[1], bf);
            }
        }
        __syncthreads();
        if (more) { stage(); __syncthreads(); }
    }

    // ---- epilogue ----
#pragma unroll
    for (int mt = 0; mt < 2; mt++) {
#pragma unroll
        for (int nt = 0; nt < 2; nt++) {
            int rbase = row0 + wm * 32 + mt * 16 + g;
            int cbase = colbase + wn * 16 + nt * 8 + tg * 2;
#pragma unroll
            for (int e = 0; e < 4; e++) {
                int r = rbase + ((e >= 2) ? 8 : 0);
                int c = cbase + (e & 1);
                float v = acc[mt][nt][e] + bias[c];
                size_t off = (size_t)r * N + c;
                if (EPI == 0) {
                    C[off] = v;
                } else if (EPI == 1) {
                    C[off] = v / (1.f + __expf(-v));
                } else if (EPI == 2) {
                    kbuf[off] = v;
                    ksum[off] = v;
                } else if (EPI == 3) {
                    kbuf[off] = v;
                    ksum[off] += 2.f * v;
                } else {  // EPI == 4
                    float t1v = ts_[r * T_ + tt];
                    float t0  = (tt == 0) ? ts_[r * T_] : ts_[r * T_ + tt - 1];
                    float dt  = (t1v - t0) * 0.25f;
                    hupd[off] += dt * (1.f / 6.f) * (ksum[off] + v);
                }
            }
        }
    }
}

// ---------------- small kernels ----------------
__global__ void zero_buf(float* p, int n) {
    int i = blockIdx.x * blockDim.x + threadIdx.x;
    if (i < n) p[i] = 0.f;
}

__global__ void pad_w1(const float* __restrict__ W1, float* __restrict__ W1p) {
    int i = blockIdx.x * blockDim.x + threadIdx.x;
    if (i < 2 * H_ * K1PAD) {
        int r = i / K1PAD, c = i - r * K1PAD;
        W1p[i] = (c < H_ + 1) ? W1[r * (H_ + 1) + c] : 0.f;
    }
}

__global__ void gru_gate(const float* __restrict__ gi, const float* __restrict__ gh,
                         float* __restrict__ h, int tt) {
    int i = blockIdx.x * blockDim.x + threadIdx.x;   // over 512*512
    if (i >= B_ * H_) return;
    int b = i >> 9, j = i & (H_ - 1);
    const float* girow = gi + (size_t)(b * T_ + tt) * (3 * H_);
    const float* ghrow = gh + (size_t)b * (3 * H_);
    float ir = girow[j], iz = girow[H_ + j], inn = girow[2 * H_ + j];
    float hr = ghrow[j], hz = ghrow[H_ + j], hn  = ghrow[2 * H_ + j];
    float r = 1.f / (1.f + expf(-(ir + hr)));
    float z = 1.f / (1.f + expf(-(iz + hz)));
    float n = tanhf(inn + r * hn);
    h[i] = (1.f - z) * n + z * h[i];
}

__global__ void finalize(const float* __restrict__ h, float* __restrict__ out) {
    int i = blockIdx.x * blockDim.x + threadIdx.x;   // over 512*512
    if (i >= B_ * H_) return;
    out[B_ * 128 + i] = h[i];                        // h
    out[B_ * 128 + B_ * H_ + i] = 0.f;               // c (stays zero)
}

// ---------------- driver ----------------
extern "C" void kernel_launch(void* const* d_in, const int* in_sizes, int n_in,
                              void* d_out, int out_size) {
    const float* x    = (const float*)d_in[0];
    const float* ts   = (const float*)d_in[1];
    const float* Wih  = (const float*)d_in[2];
    const float* Whh  = (const float*)d_in[3];
    const float* bih  = (const float*)d_in[4];
    const float* bhh  = (const float*)d_in[5];
    const float* Wout = (const float*)d_in[6];
    const float* bout = (const float*)d_in[7];
    const float* W1   = (const float*)d_in[8];
    const float* b1   = (const float*)d_in[9];
    const float* W2   = (const float*)d_in[10];
    const float* b2   = (const float*)d_in[11];
    const float* W3   = (const float*)d_in[12];
    const float* b3   = (const float*)d_in[13];
    float* dout = (float*)d_out;
    (void)in_sizes; (void)n_in;

    float *p_gi, *p_gh, *p_h, *p_z1, *p_z2, *p_kb, *p_ks, *p_w1p;
    cudaGetSymbolAddress((void**)&p_gi,  g_gi);
    cudaGetSymbolAddress((void**)&p_gh,  g_gh);
    cudaGetSymbolAddress((void**)&p_h,   g_h);
    cudaGetSymbolAddress((void**)&p_z1,  g_z1);
    cudaGetSymbolAddress((void**)&p_z2,  g_z2);
    cudaGetSymbolAddress((void**)&p_kb,  g_kb);
    cudaGetSymbolAddress((void**)&p_ks,  g_ks);
    cudaGetSymbolAddress((void**)&p_w1p, g_W1p);

    // Prologue: h = 0, pad W1, precompute gi = x @ Wih.T + bih for all 8 steps.
    zero_buf<<<(B_ * H_ + 255) / 256, 256>>>(p_h, B_ * H_);
    pad_w1<<<(2 * H_ * K1PAD + 255) / 256, 256>>>(W1, p_w1p);
    gemm_tc<0, 0><<<dim3(1536 / BN, (B_ * T_) / BM), 256>>>(
        x, Wih, bih, p_gi, 1536, 512,
        nullptr, 0, 0.f, 0.f, nullptr, nullptr, nullptr, nullptr);

    const dim3 g1(1024 / BN, B_ / BM);   // (16,8)
    const dim3 g2(1024 / BN, B_ / BM);   // (16,8)
    const dim3 g3(H_ / BN, B_ / BM);     // (8,8)
    const dim3 ggh(1536 / BN, B_ / BM);  // (24,8)

    for (int tt = 0; tt < T_; tt++) {
        // ---- ODE integrate: NSTEPS=4 RK4 steps ----
        for (int s = 0; s < 4; s++) {
            for (int j = 0; j < 4; j++) {
                float off = (j == 0) ? 0.f : ((j == 3) ? 1.f : 0.5f);
                float salpha = (float)s + off;
                float cc = off;
                // G1: z1 = swish([h + cc*dt*kprev | t] @ W1p.T + b1)
                gemm_tc<1, 1><<<g1, 256>>>(
                    p_h, p_w1p, b1, p_z1, 1024, K1PAD,
                    ts, tt, salpha, cc, p_kb, nullptr, nullptr, nullptr);
                // G2: z2 = swish(z1 @ W2.T + b2)
                gemm_tc<0, 1><<<g2, 256>>>(
                    p_z1, W2, b2, p_z2, 1024, 1024,
                    nullptr, 0, 0.f, 0.f, nullptr, nullptr, nullptr, nullptr);
                // G3: k = z2 @ W3.T + b3, fused RK accumulation
                if (j == 0) {
                    gemm_tc<0, 2><<<g3, 256>>>(
                        p_z2, W3, b3, nullptr, H_, 1024,
                        nullptr, 0, 0.f, 0.f, nullptr, p_kb, p_ks, nullptr);
                } else if (j < 3) {
                    gemm_tc<0, 3><<<g3, 256>>>(
                        p_z2, W3, b3, nullptr, H_, 1024,
                        nullptr, 0, 0.f, 0.f, nullptr, p_kb, p_ks, nullptr);
                } else {
                    gemm_tc<0, 4><<<g3, 256>>>(
                        p_z2, W3, b3, nullptr, H_, 1024,
                        ts, tt, 0.f, 0.f, nullptr, nullptr, p_ks, p_h);
                }
            }
        }
        // ---- GRU cell ----
        gemm_tc<0, 0><<<ggh, 256>>>(
            p_h, Whh, bhh, p_gh, 1536, 512,
            nullptr, 0, 0.f, 0.f, nullptr, nullptr, nullptr, nullptr);
        gru_gate<<<(B_ * H_ + 255) / 256, 256>>>(p_gi, p_gh, p_h, tt);
    }

    // ---- outputs: outs[-1] = h @ Wout.T + bout, then h, then c (zeros) ----
    gemm_tc<0, 0><<<dim3(128 / BN, B_ / BM), 256>>>(
        p_h, Wout, bout, dout, 128, 512,
        nullptr, 0, 0.f, 0.f, nullptr, nullptr, nullptr, nullptr);
    if (out_size >= B_ * 128 + 2 * B_ * H_)
        finalize<<<(B_ * H_ + 255) / 256, 256>>>(p_h, dout);
}

// round 8
// speedup vs baseline: 1.0337x; 1.0337x over previous
#include <cuda_runtime.h>
#include <math.h>

#define B_    512
#define T_    8
#define H_    512
#define K1PAD 544
#define NCTA  128
#define NTHR  128

#define BM  64
#define BN  64
#define BK  32
#define SST 36   // 32 + 4 pad words

// ---------------- scratch (static device globals; no allocation) ----------------
__device__ float g_a1[B_ * K1PAD];        // ODE GEMM1 input, tf32 values
__device__ float g_z1[B_ * 1024];         // tf32 values
__device__ float g_z2[B_ * 1024];         // tf32 values
__device__ float g_ks[B_ * H_];           // RK weighted sum, fp32
__device__ float g_h [B_ * H_];           // hidden state, fp32
__device__ float g_gi[B_ * T_ * 1536];    // precomputed input gates, fp32
__device__ float g_gh[B_ * 1536];         // hidden gates, fp32
__device__ float g_W1p [1024 * K1PAD];    // weights, tf32 values
__device__ float g_W2t [1024 * 1024];
__device__ float g_W3t [H_ * 1024];
__device__ float g_Whht[1536 * H_];
__device__ float g_Wiht[1536 * H_];
__device__ float g_Woutt[128 * H_];
__device__ float g_xt[B_ * T_ * H_];      // x converted to tf32
__device__ unsigned g_cnt;
__device__ volatile unsigned g_gen;

// ---------------- helpers ----------------
__device__ __forceinline__ unsigned f2tf(float f) {
    unsigned u;
    asm("cvt.rna.tf32.f32 %0, %1;" : "=r"(u) : "f"(f));
    return u;
}

__device__ __forceinline__ void mma8(float* c, const unsigned* a, const unsigned* b) {
    asm volatile(
        "mma.sync.aligned.m16n8k8.row.col.f32.tf32.tf32.f32 "
        "{%0,%1,%2,%3}, {%4,%5,%6,%7}, {%8,%9}, {%0,%1,%2,%3};"
        : "+f"(c[0]), "+f"(c[1]), "+f"(c[2]), "+f"(c[3])
        : "r"(a[0]), "r"(a[1]), "r"(a[2]), "r"(a[3]), "r"(b[0]), "r"(b[1]));
}

__device__ __forceinline__ void cpa16(unsigned d, const float* s) {
    asm volatile("cp.async.cg.shared.global [%0], [%1], 16;" :: "r"(d), "l"(s));
}
__device__ __forceinline__ void cpcommit() { asm volatile("cp.async.commit_group;"); }
__device__ __forceinline__ void cpwait0()  { asm volatile("cp.async.wait_group 0;" ::: "memory"); }

// Software grid barrier; targets are relative to g_gen at kernel start so
// state carries safely across graph replays (monotonic generation counter).
// ALL threads fence before arrival so every thread's global writes are
// device-visible before the release is published (no cumulativity doubt).
__device__ __forceinline__ void grid_bar(unsigned target) {
    __syncthreads();
    __threadfence();
    __syncthreads();
    if (threadIdx.x == 0) {
        unsigned a = atomicAdd(&g_cnt, 1u);
        if (a == NCTA - 1) {
            atomicExch(&g_cnt, 0u);
            __threadfence();
            g_gen = target;
        } else {
            while ((int)(g_gen - target) < 0) __nanosleep(32);
            __threadfence();
        }
    }
    __syncthreads();
}

// ---------------- GEMM phase (persistent-kernel device function) ----------------
// C-tile = A[M,K] @ Wt[N,K]^T + bias, operands already tf32 in gmem,
// cp.async double-buffered, 64x64 CTA tile, 4 warps of 32x32.
template<typename F>
__device__ __forceinline__ void gemm_tiles(
    const float* __restrict__ A, int lda,
    const float* __restrict__ Wt,
    const float* __restrict__ bias,
    int N, int K, int ntiles,
    const unsigned* sA, const unsigned* sB, unsigned sAu, unsigned sBu,
    F epi)
{
    const int tid  = threadIdx.x;
    const int lane = tid & 31, warp = tid >> 5;
    const int wm = warp >> 1, wn = warp & 1;
    const int g = lane >> 2, tg = lane & 3;
    const int ncol = N / BN;
    const int nch  = K / BK;

    for (int tile = blockIdx.x; tile < ntiles; tile += NCTA) {
        const int row0 = (tile / ncol) * BM;
        const int col0 = (tile % ncol) * BN;
        __syncthreads();  // previous tile's smem reads complete

        // prefetch chunk 0 -> buffer 0
        {
            const float* Ab = A  + (size_t)row0 * lda;
            const float* Bb = Wt + (size_t)col0 * K;
#pragma unroll
            for (int i = 0; i < 4; i++) {
                int lin = tid + i * NTHR; int r = lin >> 3, c4 = (lin & 7) * 4;
                cpa16(sAu + (unsigned)(r * SST + c4) * 4u, Ab + (size_t)r * lda + c4);
            }
#pragma unroll
            for (int i = 0; i < 4; i++) {
                int lin = tid + i * NTHR; int r = lin >> 3, c4 = (lin & 7) * 4;
                cpa16(sBu + (unsigned)(r * SST + c4) * 4u, Bb + (size_t)r * K + c4);
            }
            cpcommit();
        }

        float acc[2][4][4];
#pragma unroll
        for (int a = 0; a < 2; a++)
#pragma unroll
            for (int b = 0; b < 4; b++)
#pragma unroll
                for (int e = 0; e < 4; e++) acc[a][b][e] = 0.f;

        for (int ch = 0; ch < nch; ch++) {
            cpwait0();
            __syncthreads();
            if (ch + 1 < nch) {
                int k0 = (ch + 1) * BK;
                int bo = ((ch + 1) & 1) * (BM * SST);
                const float* Ab = A  + (size_t)row0 * lda + k0;
                const float* Bb = Wt + (size_t)col0 * K + k0;
#pragma unroll
                for (int i = 0; i < 4; i++) {
                    int lin = tid + i * NTHR; int r = lin >> 3, c4 = (lin & 7) * 4;
                    cpa16(sAu + (unsigned)(bo + r * SST + c4) * 4u, Ab + (size_t)r * lda + c4);
                }
#pragma unroll
                for (int i = 0; i < 4; i++) {
                    int lin = tid + i * NTHR; int r = lin >> 3, c4 = (lin & 7) * 4;
                    cpa16(sBu + (unsigned)(bo + r * SST + c4) * 4u, Bb + (size_t)r * K + c4);
                }
                cpcommit();
            }
            const unsigned* a_ = sA + (ch & 1) * (BM * SST);
            const unsigned* b_ = sB + (ch & 1) * (BN * SST);
#pragma unroll
            for (int ks = 0; ks < 4; ks++) {
                unsigned af[2][4];
#pragma unroll
                for (int mt = 0; mt < 2; mt++) {
                    int r = wm * 32 + mt * 16 + g;
                    int base = r * SST + ks * 8 + tg;
                    af[mt][0] = a_[base];
                    af[mt][1] = a_[base + 8 * SST];
                    af[mt][2] = a_[base + 4];
                    af[mt][3] = a_[base + 8 * SST + 4];
                }
#pragma unroll
                for (int nt = 0; nt < 4; nt++) {
                    int n = wn * 32 + nt * 8 + g;
                    unsigned bf[2];
                    bf[0] = b_[n * SST + ks * 8 + tg];
                    bf[1] = b_[n * SST + ks * 8 + tg + 4];
                    mma8(acc[0][nt], af[0], bf);
                    mma8(acc[1][nt], af[1], bf);
                }
            }
        }

#pragma unroll
        for (int mt = 0; mt < 2; mt++)
#pragma unroll
            for (int nt = 0; nt < 4; nt++)
#pragma unroll
                for (int e = 0; e < 4; e++) {
                    int r = row0 + wm * 32 + mt * 16 + g + ((e >= 2) ? 8 : 0);
                    int c = col0 + wn * 32 + nt * 8 + tg * 2 + (e & 1);
                    epi(r, c, acc[mt][nt][e] + bias[c]);
                }
    }
}

// ---------------- the persistent kernel ----------------
__global__ void __launch_bounds__(NTHR, 1)
ode_persist(const float* __restrict__ ts,  const float* __restrict__ bih,
            const float* __restrict__ bhh, const float* __restrict__ b1,
            const float* __restrict__ b2,  const float* __restrict__ b3,
            const float* __restrict__ bout, float* __restrict__ dout)
{
    __shared__ unsigned sA[2 * BM * SST];
    __shared__ unsigned sB[2 * BN * SST];
    const unsigned sAu = (unsigned)__cvta_generic_to_shared(sA);
    const unsigned sBu = (unsigned)__cvta_generic_to_shared(sB);
    const int tid = threadIdx.x, bid = blockIdx.x;

    unsigned barn = 0, barbase = 0;
    if (tid == 0) barbase = g_gen;   // stable: cannot advance before all CTAs arrive at bar 1

    // ---- phase 0: gi = x @ Wih^T + bih (all 8 steps at once) ----
    gemm_tiles(g_xt, 512, g_Wiht, bih, 1536, 512, (4096 / BM) * (1536 / BN),
               sA, sB, sAu, sBu,
               [&](int r, int c, float v) { g_gi[(size_t)r * 1536 + c] = v; });
    barn++; grid_bar(barbase + barn);

    for (int tt = 0; tt < T_; tt++) {
        for (int s = 0; s < 4; s++) {
            for (int j = 0; j < 4; j++) {
                // G1: z1 = tf32(swish(a1 @ W1p^T + b1)),  128 tiles
                gemm_tiles(g_a1, K1PAD, g_W1p, b1, 1024, K1PAD, 128,
                           sA, sB, sAu, sBu,
                           [&](int r, int c, float v) {
                               float sw = v / (1.f + __expf(-v));
                               g_z1[(size_t)r * 1024 + c] = __uint_as_float(f2tf(sw));
                           });
                barn++; grid_bar(barbase + barn);

                // G2: z2 = tf32(swish(z1 @ W2^T + b2)),  128 tiles
                gemm_tiles(g_z1, 1024, g_W2t, b2, 1024, 1024, 128,
                           sA, sB, sAu, sBu,
                           [&](int r, int c, float v) {
                               float sw = v / (1.f + __expf(-v));
                               g_z2[(size_t)r * 1024 + c] = __uint_as_float(f2tf(sw));
                           });
                barn++; grid_bar(barbase + barn);

                // G3: k = z2 @ W3^T + b3 with fused RK accumulation AND
                // construction of the next eval's A1 = tf32(h + c_next*dt*k).
                gemm_tiles(g_z2, 1024, g_W3t, b3, H_, 1024, 64,
                           sA, sB, sAu, sBu,
                           [&](int r, int c, float v) {
                               float t1 = ts[r * T_ + tt];
                               float t0 = (tt == 0) ? ts[r * T_] : ts[r * T_ + tt - 1];
                               float dt = (t1 - t0) * 0.25f;
                               int off = r * H_ + c;
                               float a1v;
                               if (j == 0)      { g_ks[off] = v;        a1v = g_h[off] + 0.5f * dt * v; }
                               else if (j == 1) { g_ks[off] += 2.f * v; a1v = g_h[off] + 0.5f * dt * v; }
                               else if (j == 2) { g_ks[off] += 2.f * v; a1v = g_h[off] + dt * v; }
                               else {
                                   float hn = g_h[off] + dt * (1.f / 6.f) * (g_ks[off] + v);
                                   g_h[off] = hn;
                                   a1v = hn;
                               }
                               g_a1[r * K1PAD + c] = __uint_as_float(f2tf(a1v));
                           });
                // idle CTAs write the next eval's t-column
                if (bid >= 64 && bid < 68) {
                    int r = (bid - 64) * NTHR + tid;
                    float t1 = ts[r * T_ + tt];
                    float t0 = (tt == 0) ? ts[r * T_] : ts[r * T_ + tt - 1];
                    float dt = (t1 - t0) * 0.25f;
                    float sn = (j < 2) ? ((float)s + 0.5f) : ((float)s + 1.f);
                    g_a1[r * K1PAD + 512] = __uint_as_float(f2tf(t0 + sn * dt));
                }
                barn++; grid_bar(barbase + barn);
            }
        }

        // GRU: gh = h @ Whh^T + bhh  (A = a1 which holds tf32(h_ode))
        gemm_tiles(g_a1, K1PAD, g_Whht, bhh, 1536, 512, (512 / BM) * (1536 / BN),
                   sA, sB, sAu, sBu,
                   [&](int r, int c, float v) { g_gh[(size_t)r * 1536 + c] = v; });
        barn++; grid_bar(barbase + barn);

        // gate: owner-tile partition matches G3 tiles so h stays same-SM.
        // At the last step, write the h output region of dout DIRECTLY from
        // registers (validated post-timing in R7).
        if (bid < 64) {
            int r0 = (bid >> 3) * 64, c0 = (bid & 7) * 64;
            for (int e = tid; e < 64 * 64; e += NTHR) {
                int r = r0 + (e >> 6), c = c0 + (e & 63);
                int off = r * H_ + c;
                size_t gio = ((size_t)(r * T_ + tt)) * 1536 + c;
                float ir  = __ldcg(&g_gi[gio]);
                float iz  = __ldcg(&g_gi[gio + 512]);
                float inn = __ldcg(&g_gi[gio + 1024]);
                size_t gho = (size_t)r * 1536 + c;
                float hr = __ldcg(&g_gh[gho]);
                float hz = __ldcg(&g_gh[gho + 512]);
                float hn = __ldcg(&g_gh[gho + 1024]);
                float hv = g_h[off];
                float rg = 1.f / (1.f + expf(-(ir + hr)));
                float zg = 1.f / (1.f + expf(-(iz + hz)));
                float ng = tanhf(inn + rg * hn);
                float h2 = (1.f - zg) * ng + zg * hv;
                g_h[off] = h2;
                g_a1[r * K1PAD + c] = __uint_as_float(f2tf(h2));
                if (tt == T_ - 1) dout[B_ * 128 + off] = h2;   // h output, direct
            }
        }
        if (bid < 4) {   // t-column for next time step: t0' = ts[:, tt]
            int r = bid * NTHR + tid;
            g_a1[r * K1PAD + 512] = __uint_as_float(f2tf(ts[r * T_ + tt]));
        }
        barn++; grid_bar(barbase + barn);
    }

    // outputs: outs[-1] = h @ Wout^T + bout (reads a1 = tf32(h_final)).
    // The c output (zeros) is written by a separate prologue kernel — the
    // R7 post-timing failure localized to tail grid-stride stores after the
    // final software barrier, so that structure is eliminated entirely.
    gemm_tiles(g_a1, K1PAD, g_Woutt, bout, 128, 512, (512 / BM) * (128 / BN),
               sA, sB, sAu, sBu,
               [&](int r, int c, float v) { dout[(size_t)r * 128 + c] = v; });
}

// ---------------- prologue kernels ----------------
__global__ void cvt_copy(const float* __restrict__ s, float* __restrict__ d, int n) {
    int i = blockIdx.x * blockDim.x + threadIdx.x;
    if (i < n) d[i] = __uint_as_float(f2tf(s[i]));
}

__global__ void pad_w1(const float* __restrict__ W1, float* __restrict__ W1p) {
    int i = blockIdx.x * blockDim.x + threadIdx.x;
    if (i < 1024 * K1PAD) {
        int r = i / K1PAD, c = i - r * K1PAD;
        W1p[i] = (c < H_ + 1) ? __uint_as_float(f2tf(W1[r * (H_ + 1) + c])) : 0.f;
    }
}

__global__ void init_state(const float* __restrict__ ts) {
    int i = blockIdx.x * blockDim.x + threadIdx.x;
    if (i < B_ * H_) g_h[i] = 0.f;
    if (i < B_ * K1PAD) {
        int r = i / K1PAD, c = i - r * K1PAD;
        g_a1[i] = (c == 512) ? __uint_as_float(f2tf(ts[r * T_])) : 0.f;
    }
}

// c output is identically zero for every call — write it in a dedicated
// kernel, decoupled from the persistent kernel.
__global__ void zero_c(float* __restrict__ dout) {
    int i = blockIdx.x * blockDim.x + threadIdx.x;
    if (i < B_ * H_) dout[B_ * 128 + B_ * H_ + i] = 0.f;
}

// ---------------- driver ----------------
extern "C" void kernel_launch(void* const* d_in, const int* in_sizes, int n_in,
                              void* d_out, int out_size) {
    const float* x    = (const float*)d_in[0];
    const float* ts   = (const float*)d_in[1];
    const float* Wih  = (const float*)d_in[2];
    const float* Whh  = (const float*)d_in[3];
    const float* bih  = (const float*)d_in[4];
    const float* bhh  = (const float*)d_in[5];
    const float* Wout = (const float*)d_in[6];
    const float* bout = (const float*)d_in[7];
    const float* W1   = (const float*)d_in[8];
    const float* b1   = (const float*)d_in[9];
    const float* W2   = (const float*)d_in[10];
    const float* b2   = (const float*)d_in[11];
    const float* W3   = (const float*)d_in[12];
    const float* b3   = (const float*)d_in[13];
    float* dout = (float*)d_out;
    (void)in_sizes; (void)n_in; (void)out_size;

    float *p_xt, *p_wih, *p_whh, *p_w2, *p_w3, *p_wout, *p_w1p;
    cudaGetSymbolAddress((void**)&p_xt,   g_xt);
    cudaGetSymbolAddress((void**)&p_wih,  g_Wiht);
    cudaGetSymbolAddress((void**)&p_whh,  g_Whht);
    cudaGetSymbolAddress((void**)&p_w2,   g_W2t);
    cudaGetSymbolAddress((void**)&p_w3,   g_W3t);
    cudaGetSymbolAddress((void**)&p_wout, g_Woutt);
    cudaGetSymbolAddress((void**)&p_w1p,  g_W1p);

    zero_c<<<(B_ * H_ + 255) / 256, 256>>>(dout);
    cvt_copy<<<(B_ * T_ * H_ + 255) / 256, 256>>>(x, p_xt, B_ * T_ * H_);
    cvt_copy<<<(1536 * H_ + 255) / 256, 256>>>(Wih, p_wih, 1536 * H_);
    cvt_copy<<<(1536 * H_ + 255) / 256, 256>>>(Whh, p_whh, 1536 * H_);
    cvt_copy<<<(1024 * 1024 + 255) / 256, 256>>>(W2, p_w2, 1024 * 1024);
    cvt_copy<<<(H_ * 1024 + 255) / 256, 256>>>(W3, p_w3, H_ * 1024);
    cvt_copy<<<(128 * H_ + 255) / 256, 256>>>(Wout, p_wout, 128 * H_);
    pad_w1<<<(1024 * K1PAD + 255) / 256, 256>>>(W1, p_w1p);
    init_state<<<(B_ * K1PAD + 255) / 256, 256>>>(ts);

    ode_persist<<<NCTA, NTHR>>>(ts, bih, bhh, b1, b2, b3, bout, dout);
}